// round 2
// baseline (speedup 1.0000x reference)
#include <cuda_runtime.h>
#include <cuda_bf16.h>
#include <cstdint>
#include <math.h>

#define NB   512
#define LL   64
#define DD   2048
#define NHD  8
#define DHD  256
#define HID  8192
#define MT   (NB*LL)   // 32768 token rows

// ---------------- scratch (device globals; allocations forbidden) -----------
__device__ float g_tokens[(size_t)MT * DD];
__device__ float g_y     [(size_t)MT * DD];
__device__ float g_qkv   [(size_t)MT * 3 * DD];
__device__ float g_z     [(size_t)MT * DD];
__device__ float g_h     [(size_t)MT * HID];
__device__ float g_ps    [MT];
__device__ float g_pooled[(size_t)NB * DD];
__device__ float g_pout  [(size_t)NB * DD];

// ---------------- helpers ----------------------------------------------------
__device__ __forceinline__ void splitbf(float v, __nv_bfloat16& h, __nv_bfloat16& l) {
    h = __float2bfloat16_rn(v);
    l = __float2bfloat16_rn(v - __bfloat162float(h));
}

__device__ __forceinline__ void mma16816(float* d, const uint32_t* a, const uint32_t* b) {
    asm volatile(
        "mma.sync.aligned.m16n8k16.row.col.f32.bf16.bf16.f32 "
        "{%0,%1,%2,%3},{%4,%5,%6,%7},{%8,%9},{%0,%1,%2,%3};"
        : "+f"(d[0]), "+f"(d[1]), "+f"(d[2]), "+f"(d[3])
        : "r"(a[0]), "r"(a[1]), "r"(a[2]), "r"(a[3]), "r"(b[0]), "r"(b[1]));
}

// ---------------- bf16x3 GEMM: C[M,N] = A[M,K] @ W[N,K]^T (+ epilogue) -------
// EPI: 0 = acc+bias ; 1 = GELU(acc+bias) ; 2 = resid + gamma*(acc+bias)
// AX : A(m,k) = x[((m>>6)*K + k)*64 + (m&63)]   (x is (B,C,H*W))
template <int EPI, bool AX>
__global__ void __launch_bounds__(256)
gemm_k(const float* __restrict__ A, const float* __restrict__ W,
       const float* __restrict__ bias, float* __restrict__ C,
       int M, int N, int K,
       const float* __restrict__ resid, const float* __restrict__ gammap)
{
    __shared__ __nv_bfloat16 Ah[128][40], Al[128][40], Bh[128][40], Bl[128][40];

    const int tid = threadIdx.x;
    const int wid = tid >> 5, lane = tid & 31;
    const int g = lane >> 2, t = lane & 3;
    const int wm = wid & 3, wn = wid >> 2;           // 4x2 warp grid, 32x64 tiles
    const int m0 = blockIdx.y * 128, n0 = blockIdx.x * 128;

    float acc[2][8][4];
#pragma unroll
    for (int i = 0; i < 2; i++)
#pragma unroll
        for (int j = 0; j < 8; j++)
#pragma unroll
            for (int r = 0; r < 4; r++) acc[i][j][r] = 0.f;

    for (int kt = 0; kt < K; kt += 32) {
        // ---- stage A tile (128 x 32) ----
        if (AX) {
            const int m  = tid & 127;
            const int kb = tid >> 7;
            const float* xb = A + (size_t)((m0 + m) >> 6) * ((size_t)K * 64) + ((m0 + m) & 63);
#pragma unroll
            for (int i = 0; i < 16; i++) {
                int kk = kb + 2 * i;
                float v = xb[(size_t)(kt + kk) * 64];
                splitbf(v, Ah[m][kk], Al[m][kk]);
            }
        } else {
            const int r = tid >> 3, k4 = (tid & 7) * 4;
#pragma unroll
            for (int i = 0; i < 4; i++) {
                int rr = r + i * 32;
                float4 v = *(const float4*)(A + (size_t)(m0 + rr) * K + kt + k4);
                splitbf(v.x, Ah[rr][k4],     Al[rr][k4]);
                splitbf(v.y, Ah[rr][k4 + 1], Al[rr][k4 + 1]);
                splitbf(v.z, Ah[rr][k4 + 2], Al[rr][k4 + 2]);
                splitbf(v.w, Ah[rr][k4 + 3], Al[rr][k4 + 3]);
            }
        }
        // ---- stage B tile (128 x 32) ----
        {
            const int r = tid >> 3, k4 = (tid & 7) * 4;
#pragma unroll
            for (int i = 0; i < 4; i++) {
                int rr = r + i * 32;
                float4 v = *(const float4*)(W + (size_t)(n0 + rr) * K + kt + k4);
                splitbf(v.x, Bh[rr][k4],     Bl[rr][k4]);
                splitbf(v.y, Bh[rr][k4 + 1], Bl[rr][k4 + 1]);
                splitbf(v.z, Bh[rr][k4 + 2], Bl[rr][k4 + 2]);
                splitbf(v.w, Bh[rr][k4 + 3], Bl[rr][k4 + 3]);
            }
        }
        __syncthreads();

#pragma unroll
        for (int ks = 0; ks < 32; ks += 16) {
            uint32_t ah[2][4], al[2][4], bh[8][2], bl[8][2];
#pragma unroll
            for (int mt = 0; mt < 2; mt++) {
                int r0 = wm * 32 + mt * 16 + g;
                ah[mt][0] = *(const uint32_t*)&Ah[r0][ks + 2 * t];
                ah[mt][1] = *(const uint32_t*)&Ah[r0 + 8][ks + 2 * t];
                ah[mt][2] = *(const uint32_t*)&Ah[r0][ks + 2 * t + 8];
                ah[mt][3] = *(const uint32_t*)&Ah[r0 + 8][ks + 2 * t + 8];
                al[mt][0] = *(const uint32_t*)&Al[r0][ks + 2 * t];
                al[mt][1] = *(const uint32_t*)&Al[r0 + 8][ks + 2 * t];
                al[mt][2] = *(const uint32_t*)&Al[r0][ks + 2 * t + 8];
                al[mt][3] = *(const uint32_t*)&Al[r0 + 8][ks + 2 * t + 8];
            }
#pragma unroll
            for (int nt = 0; nt < 8; nt++) {
                int cn = wn * 64 + nt * 8 + g;
                bh[nt][0] = *(const uint32_t*)&Bh[cn][ks + 2 * t];
                bh[nt][1] = *(const uint32_t*)&Bh[cn][ks + 2 * t + 8];
                bl[nt][0] = *(const uint32_t*)&Bl[cn][ks + 2 * t];
                bl[nt][1] = *(const uint32_t*)&Bl[cn][ks + 2 * t + 8];
            }
#pragma unroll
            for (int mt = 0; mt < 2; mt++)
#pragma unroll
                for (int nt = 0; nt < 8; nt++) {
                    mma16816(acc[mt][nt], ah[mt], bh[nt]);
                    mma16816(acc[mt][nt], ah[mt], bl[nt]);
                    mma16816(acc[mt][nt], al[mt], bh[nt]);
                }
        }
        __syncthreads();
    }

    const float gv = (EPI == 2) ? gammap[0] : 0.f;
#pragma unroll
    for (int mt = 0; mt < 2; mt++)
#pragma unroll
        for (int nt = 0; nt < 8; nt++)
#pragma unroll
            for (int c = 0; c < 4; c++) {
                int row = m0 + wm * 32 + mt * 16 + g + ((c >> 1) << 3);
                int col = n0 + wn * 64 + nt * 8 + t * 2 + (c & 1);
                float v = acc[mt][nt][c] + bias[col];
                if (EPI == 1) v = 0.5f * v * (1.f + erff(v * 0.70710678118654752f));
                if (EPI == 2) v = resid[(size_t)row * N + col] + gv * v;
                C[(size_t)row * N + col] = v;
            }
}

// ---------------- LayerNorm over D=2048, one block per row -------------------
__global__ void __launch_bounds__(256)
ln_k(const float* __restrict__ src, const float* __restrict__ gw,
     const float* __restrict__ bw, float* __restrict__ dst)
{
    __shared__ float sb[16];
    const int row = blockIdx.x, tid = threadIdx.x;
    const float* p = src + (size_t)row * DD;
    float v[8], s = 0.f, q = 0.f;
#pragma unroll
    for (int i = 0; i < 8; i++) {
        v[i] = p[tid + 256 * i];
        s += v[i]; q += v[i] * v[i];
    }
#pragma unroll
    for (int o = 16; o; o >>= 1) {
        s += __shfl_xor_sync(0xffffffffu, s, o);
        q += __shfl_xor_sync(0xffffffffu, q, o);
    }
    if ((tid & 31) == 0) { sb[tid >> 5] = s; sb[8 + (tid >> 5)] = q; }
    __syncthreads();
    s = 0.f; q = 0.f;
#pragma unroll
    for (int w = 0; w < 8; w++) { s += sb[w]; q += sb[8 + w]; }
    float mu = s * (1.f / DD);
    float var = q * (1.f / DD) - mu * mu;
    float rstd = rsqrtf(var + 1e-5f);
#pragma unroll
    for (int i = 0; i < 8; i++) {
        int c = tid + 256 * i;
        dst[(size_t)row * DD + c] = (v[i] - mu) * rstd * gw[c] + bw[c];
    }
}

// ---------------- fused attention per (b,h): S=QK^T/16+bias, softmax, PV -----
#define ATTN_SMEM_FLOATS (64*257 + 32*257 + 64*65 + 240)
__global__ void __launch_bounds__(256)
attn_k(const float* __restrict__ qkv, const float* __restrict__ relb,
       float* __restrict__ z)
{
    extern __shared__ float sm[];
    float* Qs = sm;                       // 64 x 257
    float* KV = sm + 64 * 257;            // 32 x 257
    float* Ss = KV + 32 * 257;            // 64 x 65
    float* bs = Ss + 64 * 65;             // 225

    const int tid = threadIdx.x;
    const int bb = blockIdx.x >> 3, h = blockIdx.x & 7;
    const size_t base = (size_t)bb * 64 * 6144 + h * 256;

    for (int i = tid; i < 225; i += 256) bs[i] = relb[h * 225 + i];
    for (int l = 0; l < 64; l++)
        Qs[l * 257 + tid] = qkv[base + (size_t)l * 6144 + tid];
    __syncthreads();

    const int ty = tid >> 4, tx = tid & 15;

    // scores + bias
    for (int c = 0; c < 2; c++) {
        for (int j = 0; j < 32; j++)
            KV[j * 257 + tid] = qkv[base + (size_t)(c * 32 + j) * 6144 + 2048 + tid];
        __syncthreads();
        float a[4][2] = {};
        for (int k = 0; k < 256; k++) {
            float k0 = KV[(2 * tx) * 257 + k];
            float k1 = KV[(2 * tx + 1) * 257 + k];
#pragma unroll
            for (int i = 0; i < 4; i++) {
                float qv = Qs[(4 * ty + i) * 257 + k];
                a[i][0] += qv * k0; a[i][1] += qv * k1;
            }
        }
#pragma unroll
        for (int i = 0; i < 4; i++)
#pragma unroll
            for (int j = 0; j < 2; j++) {
                int row = 4 * ty + i, col = c * 32 + 2 * tx + j;
                int rel = ((row >> 3) - (col >> 3) + 7) * 15 + ((row & 7) - (col & 7) + 7);
                Ss[row * 65 + col] = a[i][j] * 0.0625f + bs[rel];
            }
        __syncthreads();
    }

    // softmax rows (8 rows per warp)
    {
        int w = tid >> 5, lane = tid & 31;
        for (int rr = 0; rr < 8; rr++) {
            int row = w * 8 + rr;
            float v0 = Ss[row * 65 + lane], v1 = Ss[row * 65 + 32 + lane];
            float m = fmaxf(v0, v1);
#pragma unroll
            for (int o = 16; o; o >>= 1) m = fmaxf(m, __shfl_xor_sync(0xffffffffu, m, o));
            float e0 = expf(v0 - m), e1 = expf(v1 - m);
            float ssum = e0 + e1;
#pragma unroll
            for (int o = 16; o; o >>= 1) ssum += __shfl_xor_sync(0xffffffffu, ssum, o);
            float inv = 1.f / ssum;
            Ss[row * 65 + lane] = e0 * inv;
            Ss[row * 65 + 32 + lane] = e1 * inv;
        }
    }
    __syncthreads();

    // O = P @ V
    float o[4][16];
#pragma unroll
    for (int i = 0; i < 4; i++)
#pragma unroll
        for (int j = 0; j < 16; j++) o[i][j] = 0.f;

    for (int c = 0; c < 2; c++) {
        for (int j = 0; j < 32; j++)
            KV[j * 257 + tid] = qkv[base + (size_t)(c * 32 + j) * 6144 + 4096 + tid];
        __syncthreads();
        for (int j32 = 0; j32 < 32; j32++) {
            float pv[4];
#pragma unroll
            for (int i = 0; i < 4; i++) pv[i] = Ss[(4 * ty + i) * 65 + c * 32 + j32];
#pragma unroll
            for (int jc = 0; jc < 16; jc++) {
                int jj = (jc + tx) & 15;
                float vv = KV[j32 * 257 + 16 * tx + jj];
#pragma unroll
                for (int i = 0; i < 4; i++) o[i][jj] += pv[i] * vv;
            }
        }
        __syncthreads();
    }

    const size_t zb = ((size_t)bb * 64) * 2048 + h * 256;
#pragma unroll
    for (int i = 0; i < 4; i++)
#pragma unroll
        for (int jj = 0; jj < 16; jj++)
            z[zb + (size_t)(4 * ty + i) * 2048 + 16 * tx + jj] = o[i][jj];
}

// ---------------- pooling: per-row score s = qp . LN(tokens) / sqrt(D) -------
__global__ void __launch_bounds__(256)
poolscore_k(const float* __restrict__ tok, const float* __restrict__ q,
            const float* __restrict__ gw, const float* __restrict__ bw,
            float* __restrict__ out)
{
    __shared__ float sb[40];
    const int row = blockIdx.x, tid = threadIdx.x;
    const float* p = tok + (size_t)row * DD;
    float s = 0, sq = 0, sqgt = 0, sqg = 0, sqb = 0;
#pragma unroll
    for (int i = 0; i < 8; i++) {
        int c = tid + 256 * i;
        float tv = p[c], qg = q[c] * gw[c];
        s += tv; sq += tv * tv; sqgt += qg * tv; sqg += qg; sqb += q[c] * bw[c];
    }
#pragma unroll
    for (int o = 16; o; o >>= 1) {
        s    += __shfl_xor_sync(0xffffffffu, s, o);
        sq   += __shfl_xor_sync(0xffffffffu, sq, o);
        sqgt += __shfl_xor_sync(0xffffffffu, sqgt, o);
        sqg  += __shfl_xor_sync(0xffffffffu, sqg, o);
        sqb  += __shfl_xor_sync(0xffffffffu, sqb, o);
    }
    int w = tid >> 5;
    if ((tid & 31) == 0) {
        sb[w] = s; sb[8 + w] = sq; sb[16 + w] = sqgt; sb[24 + w] = sqg; sb[32 + w] = sqb;
    }
    __syncthreads();
    if (tid == 0) {
        s = sq = sqgt = sqg = sqb = 0.f;
        for (int i = 0; i < 8; i++) {
            s += sb[i]; sq += sb[8 + i]; sqgt += sb[16 + i]; sqg += sb[24 + i]; sqb += sb[32 + i];
        }
        float mu = s * (1.f / DD);
        float var = sq * (1.f / DD) - mu * mu;
        float rstd = rsqrtf(var + 1e-5f);
        out[row] = (rstd * (sqgt - mu * sqg) + sqb) * 0.022097086912079608f; // 1/sqrt(2048)
    }
}

__global__ void __launch_bounds__(256)
poolcomb_k(const float* __restrict__ tok, const float* __restrict__ ps,
           float* __restrict__ pooled)
{
    __shared__ float pr[64];
    const int b = blockIdx.x, tid = threadIdx.x;
    if (tid == 0) {
        float m = -1e30f;
        for (int l = 0; l < 64; l++) m = fmaxf(m, ps[b * 64 + l]);
        float ssum = 0.f;
        for (int l = 0; l < 64; l++) { pr[l] = expf(ps[b * 64 + l] - m); ssum += pr[l]; }
        float inv = 1.f / ssum;
        for (int l = 0; l < 64; l++) pr[l] *= inv;
    }
    __syncthreads();
    float acc[8] = {0, 0, 0, 0, 0, 0, 0, 0};
    for (int l = 0; l < 64; l++) {
        float w = pr[l];
        const float* tp = tok + ((size_t)b * 64 + l) * DD;
#pragma unroll
        for (int i = 0; i < 8; i++) acc[i] += w * tp[tid + 256 * i];
    }
#pragma unroll
    for (int i = 0; i < 8; i++) pooled[(size_t)b * DD + tid + 256 * i] = acc[i];
}

__global__ void __launch_bounds__(256)
norm_k(const float* __restrict__ pin, float* __restrict__ out)
{
    __shared__ float sb[8];
    const int b = blockIdx.x, tid = threadIdx.x;
    const float* p = pin + (size_t)b * DD;
    float v[8], s = 0.f;
#pragma unroll
    for (int i = 0; i < 8; i++) { v[i] = p[tid + 256 * i]; s += v[i] * v[i]; }
#pragma unroll
    for (int o = 16; o; o >>= 1) s += __shfl_xor_sync(0xffffffffu, s, o);
    if ((tid & 31) == 0) sb[tid >> 5] = s;
    __syncthreads();
    s = 0.f;
#pragma unroll
    for (int w = 0; w < 8; w++) s += sb[w];
    float sc = 1.f / fmaxf(sqrtf(s), 1e-12f);
#pragma unroll
    for (int i = 0; i < 8; i++) out[(size_t)b * DD + tid + 256 * i] = v[i] * sc;
}

// ---------------- launch ------------------------------------------------------
extern "C" void kernel_launch(void* const* d_in, const int* in_sizes, int n_in,
                              void* d_out, int out_size)
{
    const float* x     = (const float*)d_in[0];
    const float* in_w  = (const float*)d_in[1];
    const float* in_b  = (const float*)d_in[2];
    const float* qkv_w = (const float*)d_in[3];
    const float* qkv_b = (const float*)d_in[4];
    const float* out_w = (const float*)d_in[5];
    const float* out_b = (const float*)d_in[6];
    const float* relb  = (const float*)d_in[7];
    const float* n1g   = (const float*)d_in[8];
    const float* n1b   = (const float*)d_in[9];
    const float* n2g   = (const float*)d_in[10];
    const float* n2b   = (const float*)d_in[11];
    const float* fc1w  = (const float*)d_in[12];
    const float* fc1b  = (const float*)d_in[13];
    const float* fc2w  = (const float*)d_in[14];
    const float* fc2b  = (const float*)d_in[15];
    const float* ga    = (const float*)d_in[16];
    const float* gm    = (const float*)d_in[17];
    const float* pq    = (const float*)d_in[18];
    const float* png   = (const float*)d_in[19];
    const float* pnb   = (const float*)d_in[20];
    const float* ppw   = (const float*)d_in[21];
    const float* ppb   = (const float*)d_in[22];
    float* out = (float*)d_out;

    float *tok, *y, *qkvb, *z, *hb, *ps, *pooled, *pout;
    cudaGetSymbolAddress((void**)&tok,    g_tokens);
    cudaGetSymbolAddress((void**)&y,      g_y);
    cudaGetSymbolAddress((void**)&qkvb,   g_qkv);
    cudaGetSymbolAddress((void**)&z,      g_z);
    cudaGetSymbolAddress((void**)&hb,     g_h);
    cudaGetSymbolAddress((void**)&ps,     g_ps);
    cudaGetSymbolAddress((void**)&pooled, g_pooled);
    cudaGetSymbolAddress((void**)&pout,   g_pout);

    static bool attr_done = false;
    if (!attr_done) {
        cudaFuncSetAttribute(attn_k, cudaFuncAttributeMaxDynamicSharedMemorySize,
                             ATTN_SMEM_FLOATS * 4);
        attr_done = true;
    }

    dim3 blk(256);

    // 1. tokens = X' @ in_proj_w^T + b    (X' read directly from (B,C,HW) layout)
    gemm_k<0, true><<<dim3(16, 256), blk>>>(x, in_w, in_b, tok, MT, DD, DD, nullptr, nullptr);
    // 2. y = LN1(tokens)
    ln_k<<<MT, blk>>>(tok, n1g, n1b, y);
    // 3. qkv = y @ qkv_w^T + b
    gemm_k<0, false><<<dim3(48, 256), blk>>>(y, qkv_w, qkv_b, qkvb, MT, 3 * DD, DD, nullptr, nullptr);
    // 4. attention -> z
    attn_k<<<NB * NHD, blk, ATTN_SMEM_FLOATS * 4>>>(qkvb, relb, z);
    // 5. tokens += gamma_attn * (z @ out_w^T + b)
    gemm_k<2, false><<<dim3(16, 256), blk>>>(z, out_w, out_b, tok, MT, DD, DD, tok, ga);
    // 6. y = LN2(tokens)
    ln_k<<<MT, blk>>>(tok, n2g, n2b, y);
    // 7. h = GELU(y @ fc1^T + b)
    gemm_k<1, false><<<dim3(64, 256), blk>>>(y, fc1w, fc1b, hb, MT, HID, DD, nullptr, nullptr);
    // 8. tokens += gamma_mlp * (h @ fc2^T + b)
    gemm_k<2, false><<<dim3(16, 256), blk>>>(hb, fc2w, fc2b, tok, MT, DD, HID, tok, gm);
    // 9-10. attention pooling
    poolscore_k<<<MT, blk>>>(tok, pq, png, pnb, ps);
    poolcomb_k<<<NB, blk>>>(tok, ps, pooled);
    // 11. pooled @ pool_proj^T + b
    gemm_k<0, false><<<dim3(16, 4), blk>>>(pooled, ppw, ppb, pout, NB, DD, DD, nullptr, nullptr);
    // 12. L2 normalize
    norm_k<<<NB, blk>>>(pout, out);
}

// round 3
// speedup vs baseline: 1.0083x; 1.0083x over previous
#include <cuda_runtime.h>
#include <cuda_bf16.h>
#include <cstdint>
#include <math.h>

#define NB   512
#define LL   64
#define DD   2048
#define NHD  8
#define DHD  256
#define HID  8192
#define MT   (NB*LL)   // 32768 token rows

// ---------------- scratch (device globals; allocations forbidden) -----------
__device__ float g_tokens[(size_t)MT * DD];
__device__ float g_y     [(size_t)MT * DD];
__device__ float g_qkv   [(size_t)MT * 3 * DD];
__device__ float g_z     [(size_t)MT * DD];
__device__ float g_h     [(size_t)MT * HID];
__device__ float g_ps    [MT];
__device__ float g_pooled[(size_t)NB * DD];
__device__ float g_pout  [(size_t)NB * DD];

// ---------------- helpers ----------------------------------------------------
__device__ __forceinline__ void splitbf(float v, __nv_bfloat16& h, __nv_bfloat16& l) {
    h = __float2bfloat16_rn(v);
    l = __float2bfloat16_rn(v - __bfloat162float(h));
}

__device__ __forceinline__ void mma16816(float* d, const uint32_t* a, const uint32_t* b) {
    asm volatile(
        "mma.sync.aligned.m16n8k16.row.col.f32.bf16.bf16.f32 "
        "{%0,%1,%2,%3},{%4,%5,%6,%7},{%8,%9},{%0,%1,%2,%3};"
        : "+f"(d[0]), "+f"(d[1]), "+f"(d[2]), "+f"(d[3])
        : "r"(a[0]), "r"(a[1]), "r"(a[2]), "r"(a[3]), "r"(b[0]), "r"(b[1]));
}

// ---------------- bf16x3 GEMM: C[M,N] = A[M,K] @ W[N,K]^T (+ epilogue) -------
// EPI: 0 = acc+bias ; 1 = GELU(acc+bias) ; 2 = resid + gamma*(acc+bias)
// AX : A(m,k) = x[((m>>6)*K + k)*64 + (m&63)]   (x is (B,C,H*W))
template <int EPI, bool AX>
__global__ void __launch_bounds__(256)
gemm_k(const float* __restrict__ A, const float* __restrict__ W,
       const float* __restrict__ bias, float* __restrict__ C,
       int M, int N, int K,
       const float* __restrict__ resid, const float* __restrict__ gammap)
{
    __shared__ __nv_bfloat16 Ah[128][40], Al[128][40], Bh[128][40], Bl[128][40];

    const int tid = threadIdx.x;
    const int wid = tid >> 5, lane = tid & 31;
    const int g = lane >> 2, t = lane & 3;
    const int wm = wid & 3, wn = wid >> 2;           // 4x2 warp grid, 32x64 tiles
    const int m0 = blockIdx.y * 128, n0 = blockIdx.x * 128;

    float acc[2][8][4];
#pragma unroll
    for (int i = 0; i < 2; i++)
#pragma unroll
        for (int j = 0; j < 8; j++)
#pragma unroll
            for (int r = 0; r < 4; r++) acc[i][j][r] = 0.f;

    for (int kt = 0; kt < K; kt += 32) {
        // ---- stage A tile (128 x 32) ----
        if (AX) {
            const int m  = tid & 127;
            const int kb = tid >> 7;
            const float* xb = A + (size_t)((m0 + m) >> 6) * ((size_t)K * 64) + ((m0 + m) & 63);
#pragma unroll
            for (int i = 0; i < 16; i++) {
                int kk = kb + 2 * i;
                float v = xb[(size_t)(kt + kk) * 64];
                splitbf(v, Ah[m][kk], Al[m][kk]);
            }
        } else {
            const int r = tid >> 3, k4 = (tid & 7) * 4;
#pragma unroll
            for (int i = 0; i < 4; i++) {
                int rr = r + i * 32;
                float4 v = *(const float4*)(A + (size_t)(m0 + rr) * K + kt + k4);
                splitbf(v.x, Ah[rr][k4],     Al[rr][k4]);
                splitbf(v.y, Ah[rr][k4 + 1], Al[rr][k4 + 1]);
                splitbf(v.z, Ah[rr][k4 + 2], Al[rr][k4 + 2]);
                splitbf(v.w, Ah[rr][k4 + 3], Al[rr][k4 + 3]);
            }
        }
        // ---- stage B tile (128 x 32) ----
        {
            const int r = tid >> 3, k4 = (tid & 7) * 4;
#pragma unroll
            for (int i = 0; i < 4; i++) {
                int rr = r + i * 32;
                float4 v = *(const float4*)(W + (size_t)(n0 + rr) * K + kt + k4);
                splitbf(v.x, Bh[rr][k4],     Bl[rr][k4]);
                splitbf(v.y, Bh[rr][k4 + 1], Bl[rr][k4 + 1]);
                splitbf(v.z, Bh[rr][k4 + 2], Bl[rr][k4 + 2]);
                splitbf(v.w, Bh[rr][k4 + 3], Bl[rr][k4 + 3]);
            }
        }
        __syncthreads();

#pragma unroll
        for (int ks = 0; ks < 32; ks += 16) {
            uint32_t ah[2][4], al[2][4], bh[8][2], bl[8][2];
#pragma unroll
            for (int mt = 0; mt < 2; mt++) {
                int r0 = wm * 32 + mt * 16 + g;
                ah[mt][0] = *(const uint32_t*)&Ah[r0][ks + 2 * t];
                ah[mt][1] = *(const uint32_t*)&Ah[r0 + 8][ks + 2 * t];
                ah[mt][2] = *(const uint32_t*)&Ah[r0][ks + 2 * t + 8];
                ah[mt][3] = *(const uint32_t*)&Ah[r0 + 8][ks + 2 * t + 8];
                al[mt][0] = *(const uint32_t*)&Al[r0][ks + 2 * t];
                al[mt][1] = *(const uint32_t*)&Al[r0 + 8][ks + 2 * t];
                al[mt][2] = *(const uint32_t*)&Al[r0][ks + 2 * t + 8];
                al[mt][3] = *(const uint32_t*)&Al[r0 + 8][ks + 2 * t + 8];
            }
#pragma unroll
            for (int nt = 0; nt < 8; nt++) {
                int cn = wn * 64 + nt * 8 + g;
                bh[nt][0] = *(const uint32_t*)&Bh[cn][ks + 2 * t];
                bh[nt][1] = *(const uint32_t*)&Bh[cn][ks + 2 * t + 8];
                bl[nt][0] = *(const uint32_t*)&Bl[cn][ks + 2 * t];
                bl[nt][1] = *(const uint32_t*)&Bl[cn][ks + 2 * t + 8];
            }
#pragma unroll
            for (int mt = 0; mt < 2; mt++)
#pragma unroll
                for (int nt = 0; nt < 8; nt++) {
                    mma16816(acc[mt][nt], ah[mt], bh[nt]);
                    mma16816(acc[mt][nt], ah[mt], bl[nt]);
                    mma16816(acc[mt][nt], al[mt], bh[nt]);
                }
        }
        __syncthreads();
    }

    const float gv = (EPI == 2) ? gammap[0] : 0.f;
#pragma unroll
    for (int mt = 0; mt < 2; mt++)
#pragma unroll
        for (int nt = 0; nt < 8; nt++)
#pragma unroll
            for (int c = 0; c < 4; c++) {
                int row = m0 + wm * 32 + mt * 16 + g + ((c >> 1) << 3);
                int col = n0 + wn * 64 + nt * 8 + t * 2 + (c & 1);
                float v = acc[mt][nt][c] + bias[col];
                if (EPI == 1) v = 0.5f * v * (1.f + erff(v * 0.70710678118654752f));
                if (EPI == 2) v = resid[(size_t)row * N + col] + gv * v;
                C[(size_t)row * N + col] = v;
            }
}

// ---------------- LayerNorm over D=2048, one block per row -------------------
__global__ void __launch_bounds__(256)
ln_k(const float* __restrict__ src, const float* __restrict__ gw,
     const float* __restrict__ bw, float* __restrict__ dst)
{
    __shared__ float sb[16];
    const int row = blockIdx.x, tid = threadIdx.x;
    const float* p = src + (size_t)row * DD;
    float v[8], s = 0.f, q = 0.f;
#pragma unroll
    for (int i = 0; i < 8; i++) {
        v[i] = p[tid + 256 * i];
        s += v[i]; q += v[i] * v[i];
    }
#pragma unroll
    for (int o = 16; o; o >>= 1) {
        s += __shfl_xor_sync(0xffffffffu, s, o);
        q += __shfl_xor_sync(0xffffffffu, q, o);
    }
    if ((tid & 31) == 0) { sb[tid >> 5] = s; sb[8 + (tid >> 5)] = q; }
    __syncthreads();
    s = 0.f; q = 0.f;
#pragma unroll
    for (int w = 0; w < 8; w++) { s += sb[w]; q += sb[8 + w]; }
    float mu = s * (1.f / DD);
    float var = q * (1.f / DD) - mu * mu;
    float rstd = rsqrtf(var + 1e-5f);
#pragma unroll
    for (int i = 0; i < 8; i++) {
        int c = tid + 256 * i;
        dst[(size_t)row * DD + c] = (v[i] - mu) * rstd * gw[c] + bw[c];
    }
}

// ---------------- fused attention per (b,h): S=QK^T/16+bias, softmax, PV -----
#define ATTN_SMEM_FLOATS (64*257 + 32*257 + 64*65 + 240)
__global__ void __launch_bounds__(256)
attn_k(const float* __restrict__ qkv, const float* __restrict__ relb,
       float* __restrict__ z)
{
    extern __shared__ float sm[];
    float* Qs = sm;                       // 64 x 257
    float* KV = sm + 64 * 257;            // 32 x 257
    float* Ss = KV + 32 * 257;            // 64 x 65
    float* bs = Ss + 64 * 65;             // 225

    const int tid = threadIdx.x;
    const int bb = blockIdx.x >> 3, h = blockIdx.x & 7;
    const size_t base = (size_t)bb * 64 * 6144 + h * 256;

    for (int i = tid; i < 225; i += 256) bs[i] = relb[h * 225 + i];
    for (int l = 0; l < 64; l++)
        Qs[l * 257 + tid] = qkv[base + (size_t)l * 6144 + tid];
    __syncthreads();

    const int ty = tid >> 4, tx = tid & 15;

    // scores + bias
    for (int c = 0; c < 2; c++) {
        for (int j = 0; j < 32; j++)
            KV[j * 257 + tid] = qkv[base + (size_t)(c * 32 + j) * 6144 + 2048 + tid];
        __syncthreads();
        float a[4][2] = {};
        for (int k = 0; k < 256; k++) {
            float k0 = KV[(2 * tx) * 257 + k];
            float k1 = KV[(2 * tx + 1) * 257 + k];
#pragma unroll
            for (int i = 0; i < 4; i++) {
                float qv = Qs[(4 * ty + i) * 257 + k];
                a[i][0] += qv * k0; a[i][1] += qv * k1;
            }
        }
#pragma unroll
        for (int i = 0; i < 4; i++)
#pragma unroll
            for (int j = 0; j < 2; j++) {
                int row = 4 * ty + i, col = c * 32 + 2 * tx + j;
                int rel = ((row >> 3) - (col >> 3) + 7) * 15 + ((row & 7) - (col & 7) + 7);
                Ss[row * 65 + col] = a[i][j] * 0.0625f + bs[rel];
            }
        __syncthreads();
    }

    // softmax rows (8 rows per warp)
    {
        int w = tid >> 5, lane = tid & 31;
        for (int rr = 0; rr < 8; rr++) {
            int row = w * 8 + rr;
            float v0 = Ss[row * 65 + lane], v1 = Ss[row * 65 + 32 + lane];
            float m = fmaxf(v0, v1);
#pragma unroll
            for (int o = 16; o; o >>= 1) m = fmaxf(m, __shfl_xor_sync(0xffffffffu, m, o));
            float e0 = expf(v0 - m), e1 = expf(v1 - m);
            float ssum = e0 + e1;
#pragma unroll
            for (int o = 16; o; o >>= 1) ssum += __shfl_xor_sync(0xffffffffu, ssum, o);
            float inv = 1.f / ssum;
            Ss[row * 65 + lane] = e0 * inv;
            Ss[row * 65 + 32 + lane] = e1 * inv;
        }
    }
    __syncthreads();

    // O = P @ V
    float o[4][16];
#pragma unroll
    for (int i = 0; i < 4; i++)
#pragma unroll
        for (int j = 0; j < 16; j++) o[i][j] = 0.f;

    for (int c = 0; c < 2; c++) {
        for (int j = 0; j < 32; j++)
            KV[j * 257 + tid] = qkv[base + (size_t)(c * 32 + j) * 6144 + 4096 + tid];
        __syncthreads();
        for (int j32 = 0; j32 < 32; j32++) {
            float pv[4];
#pragma unroll
            for (int i = 0; i < 4; i++) pv[i] = Ss[(4 * ty + i) * 65 + c * 32 + j32];
#pragma unroll
            for (int jc = 0; jc < 16; jc++) {
                int jj = (jc + tx) & 15;
                float vv = KV[j32 * 257 + 16 * tx + jj];
#pragma unroll
                for (int i = 0; i < 4; i++) o[i][jj] += pv[i] * vv;
            }
        }
        __syncthreads();
    }

    const size_t zb = ((size_t)bb * 64) * 2048 + h * 256;
#pragma unroll
    for (int i = 0; i < 4; i++)
#pragma unroll
        for (int jj = 0; jj < 16; jj++)
            z[zb + (size_t)(4 * ty + i) * 2048 + 16 * tx + jj] = o[i][jj];
}

// ---------------- pooling: per-row score s = qp . LN(tokens) / sqrt(D) -------
__global__ void __launch_bounds__(256)
poolscore_k(const float* __restrict__ tok, const float* __restrict__ q,
            const float* __restrict__ gw, const float* __restrict__ bw,
            float* __restrict__ out)
{
    __shared__ float sb[40];
    const int row = blockIdx.x, tid = threadIdx.x;
    const float* p = tok + (size_t)row * DD;
    float s = 0, sq = 0, sqgt = 0, sqg = 0, sqb = 0;
#pragma unroll
    for (int i = 0; i < 8; i++) {
        int c = tid + 256 * i;
        float tv = p[c], qg = q[c] * gw[c];
        s += tv; sq += tv * tv; sqgt += qg * tv; sqg += qg; sqb += q[c] * bw[c];
    }
#pragma unroll
    for (int o = 16; o; o >>= 1) {
        s    += __shfl_xor_sync(0xffffffffu, s, o);
        sq   += __shfl_xor_sync(0xffffffffu, sq, o);
        sqgt += __shfl_xor_sync(0xffffffffu, sqgt, o);
        sqg  += __shfl_xor_sync(0xffffffffu, sqg, o);
        sqb  += __shfl_xor_sync(0xffffffffu, sqb, o);
    }
    int w = tid >> 5;
    if ((tid & 31) == 0) {
        sb[w] = s; sb[8 + w] = sq; sb[16 + w] = sqgt; sb[24 + w] = sqg; sb[32 + w] = sqb;
    }
    __syncthreads();
    if (tid == 0) {
        s = sq = sqgt = sqg = sqb = 0.f;
        for (int i = 0; i < 8; i++) {
            s += sb[i]; sq += sb[8 + i]; sqgt += sb[16 + i]; sqg += sb[24 + i]; sqb += sb[32 + i];
        }
        float mu = s * (1.f / DD);
        float var = sq * (1.f / DD) - mu * mu;
        float rstd = rsqrtf(var + 1e-5f);
        out[row] = (rstd * (sqgt - mu * sqg) + sqb) * 0.022097086912079608f; // 1/sqrt(2048)
    }
}

__global__ void __launch_bounds__(256)
poolcomb_k(const float* __restrict__ tok, const float* __restrict__ ps,
           float* __restrict__ pooled)
{
    __shared__ float pr[64];
    const int b = blockIdx.x, tid = threadIdx.x;
    if (tid == 0) {
        float m = -1e30f;
        for (int l = 0; l < 64; l++) m = fmaxf(m, ps[b * 64 + l]);
        float ssum = 0.f;
        for (int l = 0; l < 64; l++) { pr[l] = expf(ps[b * 64 + l] - m); ssum += pr[l]; }
        float inv = 1.f / ssum;
        for (int l = 0; l < 64; l++) pr[l] *= inv;
    }
    __syncthreads();
    float acc[8] = {0, 0, 0, 0, 0, 0, 0, 0};
    for (int l = 0; l < 64; l++) {
        float w = pr[l];
        const float* tp = tok + ((size_t)b * 64 + l) * DD;
#pragma unroll
        for (int i = 0; i < 8; i++) acc[i] += w * tp[tid + 256 * i];
    }
#pragma unroll
    for (int i = 0; i < 8; i++) pooled[(size_t)b * DD + tid + 256 * i] = acc[i];
}

__global__ void __launch_bounds__(256)
norm_k(const float* __restrict__ pin, float* __restrict__ out)
{
    __shared__ float sb[8];
    const int b = blockIdx.x, tid = threadIdx.x;
    const float* p = pin + (size_t)b * DD;
    float v[8], s = 0.f;
#pragma unroll
    for (int i = 0; i < 8; i++) { v[i] = p[tid + 256 * i]; s += v[i] * v[i]; }
#pragma unroll
    for (int o = 16; o; o >>= 1) s += __shfl_xor_sync(0xffffffffu, s, o);
    if ((tid & 31) == 0) sb[tid >> 5] = s;
    __syncthreads();
    s = 0.f;
#pragma unroll
    for (int w = 0; w < 8; w++) s += sb[w];
    float sc = 1.f / fmaxf(sqrtf(s), 1e-12f);
#pragma unroll
    for (int i = 0; i < 8; i++) out[(size_t)b * DD + tid + 256 * i] = v[i] * sc;
}

// ---------------- launch ------------------------------------------------------
extern "C" void kernel_launch(void* const* d_in, const int* in_sizes, int n_in,
                              void* d_out, int out_size)
{
    const float* x     = (const float*)d_in[0];
    const float* in_w  = (const float*)d_in[1];
    const float* in_b  = (const float*)d_in[2];
    const float* qkv_w = (const float*)d_in[3];
    const float* qkv_b = (const float*)d_in[4];
    const float* out_w = (const float*)d_in[5];
    const float* out_b = (const float*)d_in[6];
    const float* relb  = (const float*)d_in[7];
    const float* n1g   = (const float*)d_in[8];
    const float* n1b   = (const float*)d_in[9];
    const float* n2g   = (const float*)d_in[10];
    const float* n2b   = (const float*)d_in[11];
    const float* fc1w  = (const float*)d_in[12];
    const float* fc1b  = (const float*)d_in[13];
    const float* fc2w  = (const float*)d_in[14];
    const float* fc2b  = (const float*)d_in[15];
    const float* ga    = (const float*)d_in[16];
    const float* gm    = (const float*)d_in[17];
    const float* pq    = (const float*)d_in[18];
    const float* png   = (const float*)d_in[19];
    const float* pnb   = (const float*)d_in[20];
    const float* ppw   = (const float*)d_in[21];
    const float* ppb   = (const float*)d_in[22];
    float* out = (float*)d_out;

    float *tok, *y, *qkvb, *z, *hb, *ps, *pooled, *pout;
    cudaGetSymbolAddress((void**)&tok,    g_tokens);
    cudaGetSymbolAddress((void**)&y,      g_y);
    cudaGetSymbolAddress((void**)&qkvb,   g_qkv);
    cudaGetSymbolAddress((void**)&z,      g_z);
    cudaGetSymbolAddress((void**)&hb,     g_h);
    cudaGetSymbolAddress((void**)&ps,     g_ps);
    cudaGetSymbolAddress((void**)&pooled, g_pooled);
    cudaGetSymbolAddress((void**)&pout,   g_pout);

    static bool attr_done = false;
    if (!attr_done) {
        cudaFuncSetAttribute(attn_k, cudaFuncAttributeMaxDynamicSharedMemorySize,
                             ATTN_SMEM_FLOATS * 4);
        attr_done = true;
    }

    dim3 blk(256);

    // 1. tokens = X' @ in_proj_w^T + b    (X' read directly from (B,C,HW) layout)
    gemm_k<0, true><<<dim3(16, 256), blk>>>(x, in_w, in_b, tok, MT, DD, DD, nullptr, nullptr);
    // 2. y = LN1(tokens)
    ln_k<<<MT, blk>>>(tok, n1g, n1b, y);
    // 3. qkv = y @ qkv_w^T + b
    gemm_k<0, false><<<dim3(48, 256), blk>>>(y, qkv_w, qkv_b, qkvb, MT, 3 * DD, DD, nullptr, nullptr);
    // 4. attention -> z
    attn_k<<<NB * NHD, blk, ATTN_SMEM_FLOATS * 4>>>(qkvb, relb, z);
    // 5. tokens += gamma_attn * (z @ out_w^T + b)
    gemm_k<2, false><<<dim3(16, 256), blk>>>(z, out_w, out_b, tok, MT, DD, DD, tok, ga);
    // 6. y = LN2(tokens)
    ln_k<<<MT, blk>>>(tok, n2g, n2b, y);
    // 7. h = GELU(y @ fc1^T + b)
    gemm_k<1, false><<<dim3(64, 256), blk>>>(y, fc1w, fc1b, hb, MT, HID, DD, nullptr, nullptr);
    // 8. tokens += gamma_mlp * (h @ fc2^T + b)
    gemm_k<2, false><<<dim3(16, 256), blk>>>(hb, fc2w, fc2b, tok, MT, DD, HID, tok, gm);
    // 9-10. attention pooling
    poolscore_k<<<MT, blk>>>(tok, pq, png, pnb, ps);
    poolcomb_k<<<NB, blk>>>(tok, ps, pooled);
    // 11. pooled @ pool_proj^T + b
    gemm_k<0, false><<<dim3(16, 4), blk>>>(pooled, ppw, ppb, pout, NB, DD, DD, nullptr, nullptr);
    // 12. L2 normalize
    norm_k<<<NB, blk>>>(pout, out);
}

// round 5
// speedup vs baseline: 3.4402x; 3.4118x over previous
#include <cuda_runtime.h>
#include <cuda_bf16.h>
#include <cstdint>
#include <math.h>

#define NB   512
#define DD   2048
#define HID  8192
#define MT   (NB*64)

typedef __nv_bfloat16 bf;

// ---------------- scratch ----------------------------------------------------
__device__ bf    g_wq [(size_t)3*DD*DD];
__device__ bf    g_wo [(size_t)DD*DD];
__device__ bf    g_w1 [(size_t)HID*DD];
__device__ bf    g_w2 [(size_t)DD*HID];
__device__ bf    g_wih[(size_t)DD*DD];
__device__ bf    g_wil[(size_t)DD*DD];
__device__ bf    g_wph[(size_t)DD*DD];
__device__ bf    g_wpl[(size_t)DD*DD];
__device__ bf    g_xh [(size_t)MT*DD];
__device__ bf    g_xl [(size_t)MT*DD];
__device__ bf    g_y  [(size_t)MT*DD];
__device__ bf    g_qkv[(size_t)MT*3*DD];
__device__ bf    g_z  [(size_t)MT*DD];
__device__ bf    g_h  [(size_t)MT*HID];
__device__ bf    g_ph [(size_t)NB*DD];
__device__ bf    g_pl [(size_t)NB*DD];
__device__ float g_tok[(size_t)MT*DD];
__device__ float g_ps [MT];
__device__ float g_pooled[(size_t)NB*DD];
__device__ float g_pout  [(size_t)NB*DD];

// ---------------- helpers ----------------------------------------------------
__device__ __forceinline__ uint32_t s2u(const void* p){
    uint32_t a;
    asm("{ .reg .u64 t; cvta.to.shared.u64 t, %1; cvt.u32.u64 %0, t; }" : "=r"(a) : "l"(p));
    return a;
}
__device__ __forceinline__ void cpa16(uint32_t d, const void* s){
    asm volatile("cp.async.cg.shared.global [%0], [%1], 16;" :: "r"(d), "l"(s));
}
__device__ __forceinline__ void ldm4(uint32_t* r, uint32_t a){
    asm volatile("ldmatrix.sync.aligned.m8n8.x4.shared.b16 {%0,%1,%2,%3}, [%4];"
        : "=r"(r[0]), "=r"(r[1]), "=r"(r[2]), "=r"(r[3]) : "r"(a));
}
__device__ __forceinline__ void mma16816(float* d, const uint32_t* a, uint32_t b0, uint32_t b1){
    asm volatile(
        "mma.sync.aligned.m16n8k16.row.col.f32.bf16.bf16.f32 "
        "{%0,%1,%2,%3},{%4,%5,%6,%7},{%8,%9},{%0,%1,%2,%3};"
        : "+f"(d[0]), "+f"(d[1]), "+f"(d[2]), "+f"(d[3])
        : "r"(a[0]), "r"(a[1]), "r"(a[2]), "r"(a[3]), "r"(b0), "r"(b1));
}

// ---------------- pipelined bf16 GEMM: C[M,N]=A[M,K]@W[N,K]^T + epi ----------
// tile 128x128x64, 2-stage cp.async, 8 warps (4m x 2n), warp 32x64
// EPI: 0 +bias ; 1 GELU(+bias) ; 2 resid+gam*(+bias).  OUTH: bf16 out else f32.
#define STH 72              // smem row pitch in halves (144B)
#define STG (128*STH)       // halves per tile stage
template<int EPI, bool SPLIT, bool OUTH>
__global__ void __launch_bounds__(256)
gemm_p(const bf* __restrict__ A, const bf* __restrict__ Al,
       const bf* __restrict__ W, const bf* __restrict__ Wl,
       const float* __restrict__ bias, void* __restrict__ Cv,
       const float* __restrict__ resid, const float* __restrict__ gam,
       int M, int N, int K)
{
    extern __shared__ bf smb[];
    const uint32_t asb = s2u(smb);
    const uint32_t bsb = asb + 2*STG*2;
    const uint32_t alb = asb + 4*STG*2;
    const uint32_t blb = asb + 6*STG*2;

    const int tid = threadIdx.x, wid = tid>>5, lane = tid&31;
    const int wm = wid&3, wn = wid>>2;
    const int m0 = blockIdx.y<<7, n0 = blockIdx.x<<7;
    const int g = lane>>2, qt = lane&3;

    float acc[2][8][4];
#pragma unroll
    for (int i=0;i<2;i++)
#pragma unroll
        for (int j=0;j<8;j++)
#pragma unroll
            for (int c=0;c<4;c++) acc[i][j][c]=0.f;

    const int T = K>>6;
    auto stage = [&](int t, int buf){
        const int kt = t<<6;
        const uint32_t ob = (uint32_t)buf*STG*2;
#pragma unroll
        for (int i=0;i<4;i++){
            int id = tid + i*256, rr = id>>3, c8 = id&7;
            uint32_t so = ob + rr*144 + c8*16;
            const size_t go = (size_t)rr*K + kt + c8*8;
            cpa16(asb + so, A + (size_t)m0*K + go);
            cpa16(bsb + so, W + (size_t)n0*K + go);
            if (SPLIT){
                cpa16(alb + so, Al + (size_t)m0*K + go);
                cpa16(blb + so, Wl + (size_t)n0*K + go);
            }
        }
        asm volatile("cp.async.commit_group;" ::: "memory");
    };

    stage(0, 0);
    for (int t=0; t<T; t++){
        if (t+1 < T){
            stage(t+1, (t+1)&1);
            asm volatile("cp.async.wait_group 1;" ::: "memory");
        } else {
            asm volatile("cp.async.wait_group 0;" ::: "memory");
        }
        __syncthreads();

        const uint32_t ab = asb + (uint32_t)(t&1)*STG*2;
        const uint32_t bb = bsb + (uint32_t)(t&1)*STG*2;
        const uint32_t alB = alb + (uint32_t)(t&1)*STG*2;
        const uint32_t blB = blb + (uint32_t)(t&1)*STG*2;

        const int arow = wm*32 + (lane&15);
        const int brow = wn*64 + ((lane>>4)<<3) + (lane&7);
        const int acol8 = (lane>>4)*8;
        const int bcol8 = ((lane>>3)&1)*8;
#pragma unroll
        for (int ks=0; ks<4; ks++){
            uint32_t af[2][4], bfr[4][4];
            ldm4(af[0], ab + (arow*STH + ks*16 + acol8)*2);
            ldm4(af[1], ab + ((arow+16)*STH + ks*16 + acol8)*2);
#pragma unroll
            for (int p=0;p<4;p++)
                ldm4(bfr[p], bb + ((brow + p*16)*STH + ks*16 + bcol8)*2);
#pragma unroll
            for (int mt=0;mt<2;mt++)
#pragma unroll
                for (int nt=0;nt<8;nt++)
                    mma16816(acc[mt][nt], af[mt], bfr[nt>>1][(nt&1)*2], bfr[nt>>1][(nt&1)*2+1]);
            if (SPLIT){
                uint32_t afl[2][4], bfl[4][4];
                ldm4(afl[0], alB + (arow*STH + ks*16 + acol8)*2);
                ldm4(afl[1], alB + ((arow+16)*STH + ks*16 + acol8)*2);
#pragma unroll
                for (int p=0;p<4;p++)
                    ldm4(bfl[p], blB + ((brow + p*16)*STH + ks*16 + bcol8)*2);
#pragma unroll
                for (int mt=0;mt<2;mt++)
#pragma unroll
                    for (int nt=0;nt<8;nt++){
                        mma16816(acc[mt][nt], af[mt],  bfl[nt>>1][(nt&1)*2], bfl[nt>>1][(nt&1)*2+1]);
                        mma16816(acc[mt][nt], afl[mt], bfr[nt>>1][(nt&1)*2], bfr[nt>>1][(nt&1)*2+1]);
                    }
            }
        }
        __syncthreads();
    }

    const float gv = (EPI==2) ? gam[0] : 0.f;
#pragma unroll
    for (int mt=0;mt<2;mt++)
#pragma unroll
        for (int nt=0;nt<8;nt++)
#pragma unroll
            for (int c=0;c<4;c++){
                int row = m0 + wm*32 + mt*16 + g + ((c>>1)<<3);
                int col = n0 + wn*64 + nt*8 + qt*2 + (c&1);
                float v = acc[mt][nt][c] + bias[col];
                if (EPI==1) v = 0.5f*v*(1.f + erff(v*0.70710678118654752f));
                if (EPI==2) v = resid[(size_t)row*N + col] + gv*v;
                if (OUTH) ((bf*)Cv)[(size_t)row*N + col] = __float2bfloat16_rn(v);
                else      ((float*)Cv)[(size_t)row*N + col] = v;
            }
}
#define SM_PLAIN (4*STG*2)
#define SM_SPLIT (8*STG*2)

// ---------------- converters --------------------------------------------------
__global__ void __launch_bounds__(256)
cvtw_k(const float* __restrict__ s, bf* __restrict__ d, int n){
    int i = (blockIdx.x*256 + threadIdx.x)*4;
    if (i >= n) return;
    float4 v = *(const float4*)(s+i);
    d[i]=__float2bfloat16_rn(v.x); d[i+1]=__float2bfloat16_rn(v.y);
    d[i+2]=__float2bfloat16_rn(v.z); d[i+3]=__float2bfloat16_rn(v.w);
}
__global__ void __launch_bounds__(256)
cvtws_k(const float* __restrict__ s, bf* __restrict__ dh, bf* __restrict__ dl, int n){
    int i = (blockIdx.x*256 + threadIdx.x)*4;
    if (i >= n) return;
    float4 v = *(const float4*)(s+i);
    float a[4] = {v.x, v.y, v.z, v.w};
#pragma unroll
    for (int j=0;j<4;j++){
        bf h = __float2bfloat16_rn(a[j]);
        dh[i+j] = h;
        dl[i+j] = __float2bfloat16_rn(a[j] - __bfloat162float(h));
    }
}
// x (B,C,64) -> xh/xl [(b*64+s), C]  (transpose + split)
__global__ void __launch_bounds__(256)
xsplit_k(const float* __restrict__ x, bf* __restrict__ xh, bf* __restrict__ xl){
    __shared__ float T[64][65];
    const int b = blockIdx.y, c0 = blockIdx.x*64, tid = threadIdx.x;
    {
        const int s = tid&63, cc = tid>>6;
        const float* xp = x + ((size_t)b*DD + c0)*64;
#pragma unroll
        for (int p=0;p<16;p++){ int c = cc + p*4; T[c][s] = xp[(size_t)c*64 + s]; }
    }
    __syncthreads();
    {
        const int c = tid&63, s4 = tid>>6;
#pragma unroll
        for (int p=0;p<16;p++){
            int ss = s4 + p*4;
            float v = T[c][ss];
            bf h = __float2bfloat16_rn(v);
            size_t o = ((size_t)b*64 + ss)*DD + c0 + c;
            xh[o] = h; xl[o] = __float2bfloat16_rn(v - __bfloat162float(h));
        }
    }
}

// ---------------- LayerNorm fp32 -> bf16 -------------------------------------
__global__ void __launch_bounds__(256)
ln_k(const float* __restrict__ src, const float* __restrict__ gw,
     const float* __restrict__ bw, bf* __restrict__ dst)
{
    __shared__ float sb[16];
    const int row = blockIdx.x, tid = threadIdx.x;
    const float* p = src + (size_t)row*DD;
    float v[8], s=0.f, q=0.f;
#pragma unroll
    for (int i=0;i<8;i++){ v[i]=p[tid+256*i]; s+=v[i]; q+=v[i]*v[i]; }
#pragma unroll
    for (int o=16;o;o>>=1){ s+=__shfl_xor_sync(~0u,s,o); q+=__shfl_xor_sync(~0u,q,o); }
    if ((tid&31)==0){ sb[tid>>5]=s; sb[8+(tid>>5)]=q; }
    __syncthreads();
    s=0.f; q=0.f;
#pragma unroll
    for (int w=0;w<8;w++){ s+=sb[w]; q+=sb[8+w]; }
    float mu = s*(1.f/DD), var = q*(1.f/DD)-mu*mu, rstd = rsqrtf(var+1e-5f);
#pragma unroll
    for (int i=0;i<8;i++){
        int c = tid+256*i;
        dst[(size_t)row*DD+c] = __float2bfloat16_rn((v[i]-mu)*rstd*gw[c]+bw[c]);
    }
}

// ---------------- fused attention per (b,h), bf16 I/O, fp32 math -------------
#define ATTN_SMF (64*257 + 32*257 + 64*65 + 240)
__global__ void __launch_bounds__(256)
attn_k(const bf* __restrict__ qkv, const float* __restrict__ relb, bf* __restrict__ z)
{
    extern __shared__ float smf[];
    float* Qs = smf;
    float* KV = smf + 64*257;
    float* Ss = KV + 32*257;
    float* bs = Ss + 64*65;

    const int tid = threadIdx.x;
    const int bb = blockIdx.x>>3, h = blockIdx.x&7;
    const size_t base = (size_t)bb*64*6144 + h*256;

    for (int i=tid;i<225;i+=256) bs[i] = relb[h*225+i];
    for (int l=0;l<64;l++)
        Qs[l*257+tid] = __bfloat162float(qkv[base + (size_t)l*6144 + tid]);
    __syncthreads();

    const int ty = tid>>4, tx = tid&15;
    for (int c=0;c<2;c++){
        for (int j=0;j<32;j++)
            KV[j*257+tid] = __bfloat162float(qkv[base + (size_t)(c*32+j)*6144 + 2048 + tid]);
        __syncthreads();
        float a[4][2] = {};
        for (int k=0;k<256;k++){
            float k0 = KV[(2*tx)*257+k], k1 = KV[(2*tx+1)*257+k];
#pragma unroll
            for (int i=0;i<4;i++){
                float qv = Qs[(4*ty+i)*257+k];
                a[i][0] += qv*k0; a[i][1] += qv*k1;
            }
        }
#pragma unroll
        for (int i=0;i<4;i++)
#pragma unroll
            for (int j=0;j<2;j++){
                int row = 4*ty+i, col = c*32+2*tx+j;
                int rel = ((row>>3)-(col>>3)+7)*15 + ((row&7)-(col&7)+7);
                Ss[row*65+col] = a[i][j]*0.0625f + bs[rel];
            }
        __syncthreads();
    }
    {
        int w = tid>>5, lane = tid&31;
        for (int rr=0;rr<8;rr++){
            int row = w*8+rr;
            float v0 = Ss[row*65+lane], v1 = Ss[row*65+32+lane];
            float m = fmaxf(v0, v1);
#pragma unroll
            for (int o=16;o;o>>=1) m = fmaxf(m, __shfl_xor_sync(~0u, m, o));
            float e0 = expf(v0-m), e1 = expf(v1-m), ss = e0+e1;
#pragma unroll
            for (int o=16;o;o>>=1) ss += __shfl_xor_sync(~0u, ss, o);
            float inv = 1.f/ss;
            Ss[row*65+lane] = e0*inv; Ss[row*65+32+lane] = e1*inv;
        }
    }
    __syncthreads();

    float o[4][16];
#pragma unroll
    for (int i=0;i<4;i++)
#pragma unroll
        for (int j=0;j<16;j++) o[i][j]=0.f;
    for (int c=0;c<2;c++){
        for (int j=0;j<32;j++)
            KV[j*257+tid] = __bfloat162float(qkv[base + (size_t)(c*32+j)*6144 + 4096 + tid]);
        __syncthreads();
        for (int j32=0;j32<32;j32++){
            float pv[4];
#pragma unroll
            for (int i=0;i<4;i++) pv[i] = Ss[(4*ty+i)*65 + c*32 + j32];
#pragma unroll
            for (int jc=0;jc<16;jc++){
                int jj = (jc+tx)&15;
                float vv = KV[j32*257 + 16*tx + jj];
#pragma unroll
                for (int i=0;i<4;i++) o[i][jj] += pv[i]*vv;
            }
        }
        __syncthreads();
    }
    const size_t zb = ((size_t)bb*64)*2048 + h*256;
#pragma unroll
    for (int i=0;i<4;i++)
#pragma unroll
        for (int jj=0;jj<16;jj++)
            z[zb + (size_t)(4*ty+i)*2048 + 16*tx + jj] = __float2bfloat16_rn(o[i][jj]);
}

// ---------------- pooling ----------------------------------------------------
__global__ void __launch_bounds__(256)
poolscore_k(const float* __restrict__ tok, const float* __restrict__ q,
            const float* __restrict__ gw, const float* __restrict__ bw,
            float* __restrict__ out)
{
    __shared__ float sb[40];
    const int row = blockIdx.x, tid = threadIdx.x;
    const float* p = tok + (size_t)row*DD;
    float s=0, sq=0, sqgt=0, sqg=0, sqb=0;
#pragma unroll
    for (int i=0;i<8;i++){
        int c = tid+256*i;
        float tv = p[c], qg = q[c]*gw[c];
        s+=tv; sq+=tv*tv; sqgt+=qg*tv; sqg+=qg; sqb+=q[c]*bw[c];
    }
#pragma unroll
    for (int o=16;o;o>>=1){
        s+=__shfl_xor_sync(~0u,s,o); sq+=__shfl_xor_sync(~0u,sq,o);
        sqgt+=__shfl_xor_sync(~0u,sqgt,o); sqg+=__shfl_xor_sync(~0u,sqg,o);
        sqb+=__shfl_xor_sync(~0u,sqb,o);
    }
    int w = tid>>5;
    if ((tid&31)==0){ sb[w]=s; sb[8+w]=sq; sb[16+w]=sqgt; sb[24+w]=sqg; sb[32+w]=sqb; }
    __syncthreads();
    if (tid==0){
        s=sq=sqgt=sqg=sqb=0.f;
        for (int i=0;i<8;i++){ s+=sb[i]; sq+=sb[8+i]; sqgt+=sb[16+i]; sqg+=sb[24+i]; sqb+=sb[32+i]; }
        float mu = s*(1.f/DD), var = sq*(1.f/DD)-mu*mu, rstd = rsqrtf(var+1e-5f);
        out[row] = (rstd*(sqgt-mu*sqg)+sqb)*0.022097086912079608f;
    }
}
__global__ void __launch_bounds__(256)
poolcomb_k(const float* __restrict__ tok, const float* __restrict__ ps, float* __restrict__ pooled)
{
    __shared__ float pr[64];
    const int b = blockIdx.x, tid = threadIdx.x;
    if (tid==0){
        float m = -1e30f;
        for (int l=0;l<64;l++) m = fmaxf(m, ps[b*64+l]);
        float ss = 0.f;
        for (int l=0;l<64;l++){ pr[l] = expf(ps[b*64+l]-m); ss += pr[l]; }
        float inv = 1.f/ss;
        for (int l=0;l<64;l++) pr[l] *= inv;
    }
    __syncthreads();
    float acc[8] = {};
    for (int l=0;l<64;l++){
        float w = pr[l];
        const float* tp = tok + ((size_t)b*64+l)*DD;
#pragma unroll
        for (int i=0;i<8;i++) acc[i] += w*tp[tid+256*i];
    }
#pragma unroll
    for (int i=0;i<8;i++) pooled[(size_t)b*DD + tid+256*i] = acc[i];
}
__global__ void __launch_bounds__(256)
norm_k(const float* __restrict__ pin, float* __restrict__ out)
{
    __shared__ float sb[8];
    const int b = blockIdx.x, tid = threadIdx.x;
    const float* p = pin + (size_t)b*DD;
    float v[8], s = 0.f;
#pragma unroll
    for (int i=0;i<8;i++){ v[i]=p[tid+256*i]; s+=v[i]*v[i]; }
#pragma unroll
    for (int o=16;o;o>>=1) s += __shfl_xor_sync(~0u, s, o);
    if ((tid&31)==0) sb[tid>>5]=s;
    __syncthreads();
    s=0.f;
#pragma unroll
    for (int w=0;w<8;w++) s += sb[w];
    float sc = 1.f/fmaxf(sqrtf(s), 1e-12f);
#pragma unroll
    for (int i=0;i<8;i++) out[(size_t)b*DD + tid+256*i] = v[i]*sc;
}

// ---------------- launch ------------------------------------------------------
extern "C" void kernel_launch(void* const* d_in, const int* in_sizes, int n_in,
                              void* d_out, int out_size)
{
    const float* x     = (const float*)d_in[0];
    const float* in_w  = (const float*)d_in[1];
    const float* in_b  = (const float*)d_in[2];
    const float* qkv_w = (const float*)d_in[3];
    const float* qkv_b = (const float*)d_in[4];
    const float* out_w = (const float*)d_in[5];
    const float* out_b = (const float*)d_in[6];
    const float* relb  = (const float*)d_in[7];
    const float* n1g   = (const float*)d_in[8];
    const float* n1b   = (const float*)d_in[9];
    const float* n2g   = (const float*)d_in[10];
    const float* n2b   = (const float*)d_in[11];
    const float* fc1w  = (const float*)d_in[12];
    const float* fc1b  = (const float*)d_in[13];
    const float* fc2w  = (const float*)d_in[14];
    const float* fc2b  = (const float*)d_in[15];
    const float* ga    = (const float*)d_in[16];
    const float* gm    = (const float*)d_in[17];
    const float* pq    = (const float*)d_in[18];
    const float* png   = (const float*)d_in[19];
    const float* pnb   = (const float*)d_in[20];
    const float* ppw   = (const float*)d_in[21];
    const float* ppb   = (const float*)d_in[22];
    float* out = (float*)d_out;

    bf *wq,*wo,*w1,*w2,*wih,*wil,*wph,*wpl,*xh,*xl,*y,*qkvb,*z,*hb,*ph,*pl;
    float *tok,*ps,*pooled,*pout;
    cudaGetSymbolAddress((void**)&wq, g_wq);   cudaGetSymbolAddress((void**)&wo, g_wo);
    cudaGetSymbolAddress((void**)&w1, g_w1);   cudaGetSymbolAddress((void**)&w2, g_w2);
    cudaGetSymbolAddress((void**)&wih, g_wih); cudaGetSymbolAddress((void**)&wil, g_wil);
    cudaGetSymbolAddress((void**)&wph, g_wph); cudaGetSymbolAddress((void**)&wpl, g_wpl);
    cudaGetSymbolAddress((void**)&xh, g_xh);   cudaGetSymbolAddress((void**)&xl, g_xl);
    cudaGetSymbolAddress((void**)&y, g_y);     cudaGetSymbolAddress((void**)&qkvb, g_qkv);
    cudaGetSymbolAddress((void**)&z, g_z);     cudaGetSymbolAddress((void**)&hb, g_h);
    cudaGetSymbolAddress((void**)&ph, g_ph);   cudaGetSymbolAddress((void**)&pl, g_pl);
    cudaGetSymbolAddress((void**)&tok, g_tok); cudaGetSymbolAddress((void**)&ps, g_ps);
    cudaGetSymbolAddress((void**)&pooled, g_pooled); cudaGetSymbolAddress((void**)&pout, g_pout);

    static bool done = false;
    if (!done){
        cudaFuncSetAttribute(attn_k, cudaFuncAttributeMaxDynamicSharedMemorySize, ATTN_SMF*4);
        cudaFuncSetAttribute(gemm_p<0,true ,false>, cudaFuncAttributeMaxDynamicSharedMemorySize, SM_SPLIT);
        cudaFuncSetAttribute(gemm_p<0,false,true >, cudaFuncAttributeMaxDynamicSharedMemorySize, SM_PLAIN);
        cudaFuncSetAttribute(gemm_p<1,false,true >, cudaFuncAttributeMaxDynamicSharedMemorySize, SM_PLAIN);
        cudaFuncSetAttribute(gemm_p<2,false,false>, cudaFuncAttributeMaxDynamicSharedMemorySize, SM_PLAIN);
        done = true;
    }

    dim3 blk(256);
    // weight conversions
    cvtw_k <<<(3*DD*DD/4+255)/256, blk>>>(qkv_w, wq, 3*DD*DD);
    cvtw_k <<<(DD*DD/4+255)/256,   blk>>>(out_w, wo, DD*DD);
    cvtw_k <<<(HID*DD/4+255)/256,  blk>>>(fc1w,  w1, HID*DD);
    cvtw_k <<<(DD*HID/4+255)/256,  blk>>>(fc2w,  w2, DD*HID);
    cvtws_k<<<(DD*DD/4+255)/256,   blk>>>(in_w, wih, wil, DD*DD);
    cvtws_k<<<(DD*DD/4+255)/256,   blk>>>(ppw,  wph, wpl, DD*DD);
    // x transpose + split
    xsplit_k<<<dim3(32, NB), blk>>>(x, xh, xl);

    // 1. tokens = X @ in_w^T + b   (split)
    gemm_p<0,true,false><<<dim3(16,256), blk, SM_SPLIT>>>(xh, xl, wih, wil, in_b, tok, nullptr, nullptr, MT, DD, DD);
    // 2. y = LN1(tokens)
    ln_k<<<MT, blk>>>(tok, n1g, n1b, y);
    // 3. qkv
    gemm_p<0,false,true><<<dim3(48,256), blk, SM_PLAIN>>>(y, nullptr, wq, nullptr, qkv_b, qkvb, nullptr, nullptr, MT, 3*DD, DD);
    // 4. attention
    attn_k<<<NB*8, blk, ATTN_SMF*4>>>(qkvb, relb, z);
    // 5. tokens += ga*(z @ out_w^T + b)
    gemm_p<2,false,false><<<dim3(16,256), blk, SM_PLAIN>>>(z, nullptr, wo, nullptr, out_b, tok, tok, ga, MT, DD, DD);
    // 6. y = LN2(tokens)
    ln_k<<<MT, blk>>>(tok, n2g, n2b, y);
    // 7. h = GELU(y @ fc1^T + b)
    gemm_p<1,false,true><<<dim3(64,256), blk, SM_PLAIN>>>(y, nullptr, w1, nullptr, fc1b, hb, nullptr, nullptr, MT, HID, DD);
    // 8. tokens += gm*(h @ fc2^T + b)
    gemm_p<2,false,false><<<dim3(16,256), blk, SM_PLAIN>>>(hb, nullptr, w2, nullptr, fc2b, tok, tok, gm, MT, DD, HID);
    // 9-10. pooling
    poolscore_k<<<MT, blk>>>(tok, pq, png, pnb, ps);
    poolcomb_k<<<NB, blk>>>(tok, ps, pooled);
    cvtws_k<<<(NB*DD/4+255)/256, blk>>>(pooled, ph, pl, NB*DD);
    // 11. pout = pooled @ pool_w^T + b (split)
    gemm_p<0,true,false><<<dim3(16,4), blk, SM_SPLIT>>>(ph, pl, wph, wpl, ppb, pout, nullptr, nullptr, NB, DD, DD);
    // 12. normalize
    norm_k<<<NB, blk>>>(pout, out);
}